// round 16
// baseline (speedup 1.0000x reference)
#include <cuda_runtime.h>
#include <cuda_fp16.h>
#include <stdint.h>
#include <math.h>

// Fixed problem dims
#define NB   8
#define SEQB 2048
#define DIMQ 1024

static constexpr size_t XE = (size_t)NB * SEQB * DIMQ;   // 16,777,216
static constexpr size_t WE = (size_t)DIMQ * DIMQ;        // 1,048,576
static constexpr size_t SE = (size_t)NB * SEQB * SEQB;   // 33,554,432

// Scratch (__device__ globals: allocation-free rule). All fp16.
__device__ __half g_x[XE];
__device__ __half g_wq[WE], g_wk[WE], g_wv[WE];
__device__ __half g_Q[XE], g_K[XE], g_Vt[XE];
__device__ __half g_E[SE];                   // exp(QK^T/32), unnormalized, causal-masked
__device__ float  g_sum[(size_t)NB * SEQB];  // row sums (atomic-accumulated by scores)

// ---------------------------------------------------------------------------
// PTX helpers (baseline PTX only — no 'a'-gated features)
// ---------------------------------------------------------------------------
__device__ __forceinline__ uint32_t smem_u32(const void* p) {
    uint32_t a;
    asm("{ .reg .u64 t; cvta.to.shared.u64 t, %1; cvt.u32.u64 %0, t; }"
        : "=r"(a) : "l"(p));
    return a;
}

__device__ __forceinline__ void ldsm_x4(uint32_t addr, uint32_t& r0, uint32_t& r1,
                                        uint32_t& r2, uint32_t& r3) {
    asm volatile("ldmatrix.sync.aligned.m8n8.x4.shared.b16 {%0,%1,%2,%3}, [%4];"
                 : "=r"(r0), "=r"(r1), "=r"(r2), "=r"(r3) : "r"(addr));
}

__device__ __forceinline__ void mma16816(float& d0, float& d1, float& d2, float& d3,
                                         uint32_t a0, uint32_t a1, uint32_t a2, uint32_t a3,
                                         uint32_t b0, uint32_t b1) {
    asm volatile(
        "mma.sync.aligned.m16n8k16.row.col.f32.f16.f16.f32 "
        "{%0,%1,%2,%3}, {%4,%5,%6,%7}, {%8,%9}, {%0,%1,%2,%3};"
        : "+f"(d0), "+f"(d1), "+f"(d2), "+f"(d3)
        : "r"(a0), "r"(a1), "r"(a2), "r"(a3), "r"(b0), "r"(b1));
}

// ---------------------------------------------------------------------------
// GEMM-NT core: C[128,128] tile at (m0,n0) = sum_k A[m,k]*B[n,k], fp32 accum.
// 128 threads = 4 warps (2m x 2n), warp tile 64x64 (8 ldsm : 32 mma =
// 128 B LDS per MMA, vs 192 for 64x32). B-fragments staged in two halves so
// peak regs ~165 -> 3 CTAs/SM via __launch_bounds__(128,3).
// BK=32 (64B rows, row-pair XOR swizzle), 3-stage cp.async ring, depth 2.
// Epilogue modes:
//   2: fp16 store                                    (projections)
//   3: fp16 exp(d*alpha), causal mask, atomic rowsum (scores -> E, g_sum)
//   4: fp32 store d / aux[row]                       (out, row-normalized)
// ---------------------------------------------------------------------------
#define STAGES  3
#define TILE_B  8192                        // 128 rows x 64 bytes
#define CHUNK_B (2 * TILE_B)                // A, B
#define SMEM_SZ (STAGES * CHUNK_B)          // 49152 -> 3 CTAs/SM = 147KB

__device__ __forceinline__ void gemm128_nt(
    const __half* __restrict__ A, const __half* __restrict__ B,
    int lda, int ldb, int kb32, int m0, int n0, int ldc,
    float* __restrict__ C32, __half* __restrict__ C16,
    float* __restrict__ aux,
    float alpha, int mode)
{
    extern __shared__ char smem[];
    const uint32_t sbase = smem_u32(smem);
    const int tid  = threadIdx.x;
    const int wid  = tid >> 5;
    const int lane = tid & 31;
    const int wm = wid >> 1;      // 0..1 (64-row slab)
    const int wn = wid & 1;       // 0..1 (64-col slab)

    auto load_chunk = [&](int c, int s) {
        const int k0 = c * 32;
        const uint32_t st = sbase + s * CHUNK_B;
#pragma unroll
        for (int i = 0; i < 4; i++) {
            int o = tid + i * 128;            // 0..511 : 128 rows x 4 x 16B
            int row = o >> 2, seg = o & 3;
            uint32_t off = (uint32_t)(o << 4);
            uint32_t sw = off ^ ((((uint32_t)row >> 1) & 3u) << 4);
            const __half* ga = A + (size_t)(m0 + row) * lda + k0 + seg * 8;
            const __half* gb = B + (size_t)(n0 + row) * ldb + k0 + seg * 8;
            asm volatile("cp.async.cg.shared.global [%0], [%1], 16;" :: "r"(st + sw),          "l"(ga));
            asm volatile("cp.async.cg.shared.global [%0], [%1], 16;" :: "r"(st + TILE_B + sw), "l"(gb));
        }
        asm volatile("cp.async.commit_group;" ::: "memory");
    };

    float acc[4][8][4];
#pragma unroll
    for (int i = 0; i < 4; i++)
#pragma unroll
        for (int j = 0; j < 8; j++)
#pragma unroll
            for (int k = 0; k < 4; k++) acc[i][j][k] = 0.f;

    // Prologue: 2 chunks in flight (kb32 >= 4 at all call sites)
    load_chunk(0, 0);
    load_chunk(1, 1);

    const int lrow = lane & 15;
    const int lhi  = (lane >> 4) & 1;

    for (int c = 0; c < kb32; c++) {
        const int s = c % STAGES;
        asm volatile("cp.async.wait_group 1;" ::: "memory");   // chunk c resident
        __syncthreads();

        const int nxt = c + 2;
        if (nxt < kb32) load_chunk(nxt, nxt % STAGES);
        else asm volatile("cp.async.commit_group;" ::: "memory");  // uniform counts

        const uint32_t st = sbase + s * CHUNK_B;
#pragma unroll
        for (int kk = 0; kk < 2; kk++) {
            const uint32_t c16 = (uint32_t)(kk * 2 + lhi);   // 16B column index
            uint32_t a[4][4], b[2][4];
#pragma unroll
            for (int mf = 0; mf < 4; mf++) {
                int row = wm * 64 + mf * 16 + lrow;
                uint32_t sw = (uint32_t)(row * 64) + ((c16 ^ (((uint32_t)row >> 1) & 3u)) << 4);
                ldsm_x4(st + sw, a[mf][0], a[mf][1], a[mf][2], a[mf][3]);
            }
#pragma unroll
            for (int h = 0; h < 2; h++) {    // two n-halves: b regs reused
#pragma unroll
                for (int nf2 = 0; nf2 < 2; nf2++) {
                    int row = wn * 64 + (h * 2 + nf2) * 16 + lrow;
                    uint32_t sw = (uint32_t)(row * 64) + ((c16 ^ (((uint32_t)row >> 1) & 3u)) << 4);
                    ldsm_x4(st + TILE_B + sw, b[nf2][0], b[nf2][1], b[nf2][2], b[nf2][3]);
                }
#pragma unroll
                for (int mf = 0; mf < 4; mf++)
#pragma unroll
                    for (int nf = 0; nf < 4; nf++) {
                        uint32_t h0 = (nf & 1) ? b[nf >> 1][1] : b[nf >> 1][0];
                        uint32_t h1 = (nf & 1) ? b[nf >> 1][3] : b[nf >> 1][2];
                        float* d = acc[mf][h * 4 + nf];
                        mma16816(d[0], d[1], d[2], d[3],
                                 a[mf][0], a[mf][1], a[mf][2], a[mf][3], h0, h1);
                    }
            }
        }
    }

    // Epilogue: straight from registers.
#pragma unroll
    for (int mf = 0; mf < 4; mf++) {
        const int r0 = m0 + wm * 64 + mf * 16 + (lane >> 2);
        float rs0 = 0.f, rs1 = 0.f;   // mode-3 row-sum partials (rows r0, r0+8)
        float iv0 = 0.f, iv1 = 0.f;
        if (mode == 4) {
            iv0 = __fdividef(1.f, aux[r0]);
            iv1 = __fdividef(1.f, aux[r0 + 8]);
        }
#pragma unroll
        for (int nf = 0; nf < 8; nf++) {
            const int col = n0 + wn * 64 + nf * 8 + (lane & 3) * 2;
            float d0 = acc[mf][nf][0], d1 = acc[mf][nf][1];
            float d2 = acc[mf][nf][2], d3 = acc[mf][nf][3];
            if (mode == 2) {
                unsigned short h0 = __half_as_ushort(__float2half_rn(d0));
                unsigned short h1 = __half_as_ushort(__float2half_rn(d1));
                unsigned short h2 = __half_as_ushort(__float2half_rn(d2));
                unsigned short h3 = __half_as_ushort(__float2half_rn(d3));
                *(uint32_t*)(C16 + (size_t)r0 * ldc + col)       = h0 | ((uint32_t)h1 << 16);
                *(uint32_t*)(C16 + (size_t)(r0 + 8) * ldc + col) = h2 | ((uint32_t)h3 << 16);
            } else if (mode == 3) {
                // exp(score) with causal mask (col > row -> 0); accumulate row sums
                float e0 = (col     <= r0    ) ? __expf(d0 * alpha) : 0.f;
                float e1 = (col + 1 <= r0    ) ? __expf(d1 * alpha) : 0.f;
                float e2 = (col     <= r0 + 8) ? __expf(d2 * alpha) : 0.f;
                float e3 = (col + 1 <= r0 + 8) ? __expf(d3 * alpha) : 0.f;
                rs0 += e0 + e1;
                rs1 += e2 + e3;
                unsigned short h0 = __half_as_ushort(__float2half_rn(e0));
                unsigned short h1 = __half_as_ushort(__float2half_rn(e1));
                unsigned short h2 = __half_as_ushort(__float2half_rn(e2));
                unsigned short h3 = __half_as_ushort(__float2half_rn(e3));
                *(uint32_t*)(C16 + (size_t)r0 * ldc + col)       = h0 | ((uint32_t)h1 << 16);
                *(uint32_t*)(C16 + (size_t)(r0 + 8) * ldc + col) = h2 | ((uint32_t)h3 << 16);
            } else {  // mode 4: fp32, row-normalized by aux[row]
                float2 u, v;
                u.x = d0 * iv0; u.y = d1 * iv0;
                v.x = d2 * iv1; v.y = d3 * iv1;
                *(float2*)(C32 + (size_t)r0 * ldc + col)       = u;
                *(float2*)(C32 + (size_t)(r0 + 8) * ldc + col) = v;
            }
        }
        if (mode == 3) {
            // lanes 4k..4k+3 share the same rows; quad-reduce then one atomic
            rs0 += __shfl_xor_sync(0xFFFFFFFF, rs0, 1);
            rs0 += __shfl_xor_sync(0xFFFFFFFF, rs0, 2);
            rs1 += __shfl_xor_sync(0xFFFFFFFF, rs1, 1);
            rs1 += __shfl_xor_sync(0xFFFFFFFF, rs1, 2);
            if ((lane & 3) == 0) {
                atomicAdd(aux + r0,     rs0);
                atomicAdd(aux + r0 + 8, rs1);
            }
        }
    }
}

// ---------------------------------------------------------------------------
// Merged prep kernel: zero g_sum + convert x and W to fp16.
// id < 16384: x blocks; next 3072: W blocks; last 16: zero g_sum.
// ---------------------------------------------------------------------------
__device__ __forceinline__ void hi4_store(float4 v, __half* dh, size_t i) {
    unsigned short h0 = __half_as_ushort(__float2half_rn(v.x));
    unsigned short h1 = __half_as_ushort(__float2half_rn(v.y));
    unsigned short h2 = __half_as_ushort(__float2half_rn(v.z));
    unsigned short h3 = __half_as_ushort(__float2half_rn(v.w));
    *(uint2*)(dh + i) = make_uint2(h0 | ((uint32_t)h1 << 16), h2 | ((uint32_t)h3 << 16));
}

__global__ __launch_bounds__(256) void k_prep(const float* __restrict__ x,
                                              const float* __restrict__ Wq,
                                              const float* __restrict__ Wk,
                                              const float* __restrict__ Wv) {
    const int id = blockIdx.x;
    if (id < 16384) {
        size_t i = ((size_t)id * 256 + threadIdx.x) * 4;
        hi4_store(*(const float4*)(x + i), g_x, i);
    } else if (id < 19456) {
        const int id2 = id - 16384;
        const int z = id2 >> 10;              // 0..2
        const int blk = id2 & 1023;
        const float* src = (z == 0) ? Wq : (z == 1) ? Wk : Wv;
        __half* dst = (z == 0) ? g_wq : (z == 1) ? g_wk : g_wv;
        size_t i = ((size_t)blk * 256 + threadIdx.x) * 4;
        hi4_store(*(const float4*)(src + i), dst, i);
    } else {
        size_t i = (size_t)(id - 19456) * 1024 + threadIdx.x * 4;
        *(float4*)(g_sum + i) = make_float4(0.f, 0.f, 0.f, 0.f);
    }
}

// ---------------------------------------------------------------------------
// Merged projections: 1D grid of 3072 CTAs (128 threads).
// ---------------------------------------------------------------------------
__global__ __launch_bounds__(128, 3) void k_proj() {
    const int id = blockIdx.x;
    if (id < 2048) {
        const int z   = id >> 10;
        const int rem = id & 1023;
        const int by  = rem >> 3;       // 0..127 (token tiles)
        const int bx  = rem & 7;        // 0..7   (out-dim tiles)
        gemm128_nt(g_x, z ? g_wk : g_wq, DIMQ, DIMQ, DIMQ / 32,
                   by * 128, bx * 128, DIMQ,
                   nullptr, z ? g_K : g_Q, nullptr, 1.f, 2);
    } else {
        const int id2 = id - 2048;
        const int b   = id2 >> 7;       // 0..7
        const int rem = id2 & 127;
        const int bx  = rem & 15;       // 0..15 (token tiles)
        const int by  = rem >> 4;       // 0..7  (v-dim tiles)
        gemm128_nt(g_wv, g_x + (size_t)b * SEQB * DIMQ, DIMQ, DIMQ, DIMQ / 32,
                   by * 128, bx * 128, SEQB,
                   nullptr, g_Vt + (size_t)b * DIMQ * SEQB, nullptr, 1.f, 2);
    }
}

// Scores: E_b = exp((Q_b @ K_b^T)/32), causal-masked, fp16 out + atomic rowsums.
// Compacted grid: blockIdx.x = triangular tile index t in [0,136), batch = y.
__global__ __launch_bounds__(128, 3) void k_scores() {
    const int t = blockIdx.x, b = blockIdx.y;
    int bm = (int)((sqrtf(8.f * (float)t + 1.f) - 1.f) * 0.5f);
    if ((bm + 1) * (bm + 2) / 2 <= t) bm++;
    else if (bm * (bm + 1) / 2 > t) bm--;
    const int bn = t - bm * (bm + 1) / 2;
    gemm128_nt(g_Q + (size_t)b * SEQB * DIMQ, g_K + (size_t)b * SEQB * DIMQ,
               DIMQ, DIMQ, DIMQ / 32, bm * 128, bn * 128, SEQB,
               nullptr, g_E + (size_t)b * SEQB * SEQB,
               g_sum + (size_t)b * SEQB, 0.03125f, 3);
}

// Out: O_b = (E_b @ Vt_b^T) / sum[row], K truncated at (bm+1)*128.
// bm reversed so the longest-K CTAs launch first (better wave packing).
__global__ __launch_bounds__(128, 3) void k_out(float* __restrict__ out) {
    const int bn = blockIdx.x, bm = 15 - blockIdx.y, b = blockIdx.z;
    gemm128_nt(g_E + (size_t)b * SEQB * SEQB, g_Vt + (size_t)b * DIMQ * SEQB,
               SEQB, SEQB, (bm + 1) * 4, bm * 128, bn * 128, DIMQ,
               out + (size_t)b * SEQB * DIMQ, nullptr,
               g_sum + (size_t)b * SEQB, 1.f, 4);
}

// ---------------------------------------------------------------------------
extern "C" void kernel_launch(void* const* d_in, const int* in_sizes, int n_in,
                              void* d_out, int out_size)
{
    const float* x  = (const float*)d_in[0];
    const float* Wq = (const float*)d_in[1];
    const float* Wk = (const float*)d_in[2];
    const float* Wv = (const float*)d_in[3];
    float* out = (float*)d_out;

    cudaFuncSetAttribute(k_proj,   cudaFuncAttributeMaxDynamicSharedMemorySize, SMEM_SZ);
    cudaFuncSetAttribute(k_scores, cudaFuncAttributeMaxDynamicSharedMemorySize, SMEM_SZ);
    cudaFuncSetAttribute(k_out,    cudaFuncAttributeMaxDynamicSharedMemorySize, SMEM_SZ);

    k_prep  <<<19472, 256>>>(x, Wq, Wk, Wv);                             // conv x/W + zero sums
    k_proj  <<<3072, 128, SMEM_SZ>>>();                                  // merged QK + Vt
    k_scores<<<dim3(136, NB), 128, SMEM_SZ>>>();                         // 136 tri tiles x 8
    k_out   <<<dim3(DIMQ / 128, SEQB / 128, NB), 128, SMEM_SZ>>>(out);   // (8,16,8)
}

// round 17
// speedup vs baseline: 1.1083x; 1.1083x over previous
#include <cuda_runtime.h>
#include <cuda_fp16.h>
#include <stdint.h>
#include <math.h>

// Fixed problem dims
#define NB   8
#define SEQB 2048
#define DIMQ 1024

static constexpr size_t XE = (size_t)NB * SEQB * DIMQ;   // 16,777,216
static constexpr size_t WE = (size_t)DIMQ * DIMQ;        // 1,048,576
static constexpr size_t SE = (size_t)NB * SEQB * SEQB;   // 33,554,432

// Scratch (__device__ globals: allocation-free rule). All fp16.
__device__ __half g_x[XE];
__device__ __half g_wq[WE], g_wk[WE], g_wv[WE];
__device__ __half g_Q[XE], g_K[XE], g_Vt[XE];
__device__ __half g_E[SE];                   // exp(QK^T/32), unnormalized, causal-masked
__device__ float  g_sum[(size_t)NB * SEQB];  // row sums (atomic-accumulated by scores)

// ---------------------------------------------------------------------------
// PTX helpers (baseline PTX only — no 'a'-gated features)
// ---------------------------------------------------------------------------
__device__ __forceinline__ uint32_t smem_u32(const void* p) {
    uint32_t a;
    asm("{ .reg .u64 t; cvta.to.shared.u64 t, %1; cvt.u32.u64 %0, t; }"
        : "=r"(a) : "l"(p));
    return a;
}

__device__ __forceinline__ void ldsm_x4(uint32_t addr, uint32_t& r0, uint32_t& r1,
                                        uint32_t& r2, uint32_t& r3) {
    asm volatile("ldmatrix.sync.aligned.m8n8.x4.shared.b16 {%0,%1,%2,%3}, [%4];"
                 : "=r"(r0), "=r"(r1), "=r"(r2), "=r"(r3) : "r"(addr));
}

__device__ __forceinline__ void mma16816(float& d0, float& d1, float& d2, float& d3,
                                         uint32_t a0, uint32_t a1, uint32_t a2, uint32_t a3,
                                         uint32_t b0, uint32_t b1) {
    asm volatile(
        "mma.sync.aligned.m16n8k16.row.col.f32.f16.f16.f32 "
        "{%0,%1,%2,%3}, {%4,%5,%6,%7}, {%8,%9}, {%0,%1,%2,%3};"
        : "+f"(d0), "+f"(d1), "+f"(d2), "+f"(d3)
        : "r"(a0), "r"(a1), "r"(a2), "r"(a3), "r"(b0), "r"(b1));
}

// ---------------------------------------------------------------------------
// GEMM-NT core, plain fp16: C[128,128] tile at (m0,n0) = sum_k A[m,k]*B[n,k]
// (fp32 accumulate). 256 threads = 8 warps (2m x 4n), warp tile 64x32,
// BK=64 (128B rows, SW128 swizzle), 3-stage cp.async ring, 2 CTAs/SM.
// This configuration is the measured optimum (R15: 60% tensor); both larger
// warp tiles (R16) and BK=32 variants (R11) measured slower.
// Epilogue modes:
//   2: fp16 store                                    (projections)
//   3: fp16 exp(d*alpha), causal mask, atomic rowsum (scores -> E, g_sum)
//   4: fp32 store d / aux[row]                       (out, row-normalized)
// ---------------------------------------------------------------------------
#define STAGES  3
#define TILE_B  16384                       // 128 rows x 128 bytes
#define CHUNK_B (2 * TILE_B)                // A, B
#define SMEM_SZ (STAGES * CHUNK_B)          // 98304

__device__ __forceinline__ void gemm128_nt(
    const __half* __restrict__ A, const __half* __restrict__ B,
    int lda, int ldb, int kb64, int m0, int n0, int ldc,
    float* __restrict__ C32, __half* __restrict__ C16,
    float* __restrict__ aux,
    float alpha, int mode)
{
    extern __shared__ char smem[];
    const uint32_t sbase = smem_u32(smem);
    const int tid  = threadIdx.x;
    const int wid  = tid >> 5;
    const int lane = tid & 31;
    const int wm = wid >> 2;      // 0..1 (64-row slab)
    const int wn = wid & 3;       // 0..3 (32-col slab)

    auto load_chunk = [&](int c, int s) {
        const int k0 = c * 64;
        const uint32_t st = sbase + s * CHUNK_B;
#pragma unroll
        for (int i = 0; i < 4; i++) {
            int o = tid + i * 256;            // 0..1023 : 128 rows x 8 x 16B
            int row = o >> 3, seg = o & 7;
            uint32_t off = (uint32_t)(o << 4);
            uint32_t sw = off ^ ((off >> 3) & 0x70);
            const __half* ga = A + (size_t)(m0 + row) * lda + k0 + seg * 8;
            const __half* gb = B + (size_t)(n0 + row) * ldb + k0 + seg * 8;
            asm volatile("cp.async.cg.shared.global [%0], [%1], 16;" :: "r"(st + sw),          "l"(ga));
            asm volatile("cp.async.cg.shared.global [%0], [%1], 16;" :: "r"(st + TILE_B + sw), "l"(gb));
        }
        asm volatile("cp.async.commit_group;" ::: "memory");
    };

    float acc[4][4][4];
#pragma unroll
    for (int i = 0; i < 4; i++)
#pragma unroll
        for (int j = 0; j < 4; j++)
#pragma unroll
            for (int k = 0; k < 4; k++) acc[i][j][k] = 0.f;

    // Prologue: 2 chunks in flight (kb64 >= 2 at all call sites)
    load_chunk(0, 0);
    load_chunk(1, 1);

    const int lrow = lane & 15;
    const int lhi  = (lane >> 4) & 1;

    for (int c = 0; c < kb64; c++) {
        const int s = c % STAGES;
        asm volatile("cp.async.wait_group 1;" ::: "memory");   // chunk c resident
        __syncthreads();

        const int nxt = c + 2;
        if (nxt < kb64) load_chunk(nxt, nxt % STAGES);
        else asm volatile("cp.async.commit_group;" ::: "memory");  // uniform counts

        const uint32_t st = sbase + s * CHUNK_B;
#pragma unroll
        for (int kk = 0; kk < 4; kk++) {
            const uint32_t col = (uint32_t)(kk * 32 + lhi * 16);   // byte column
            uint32_t a[4][4], b[2][4];
#pragma unroll
            for (int mf = 0; mf < 4; mf++) {
                int row = wm * 64 + mf * 16 + lrow;
                uint32_t addr = st + row * 128 + (col ^ ((row & 7) << 4));
                ldsm_x4(addr, a[mf][0], a[mf][1], a[mf][2], a[mf][3]);
            }
#pragma unroll
            for (int nf2 = 0; nf2 < 2; nf2++) {
                int row = wn * 32 + nf2 * 16 + lrow;
                uint32_t addr = st + TILE_B + row * 128 + (col ^ ((row & 7) << 4));
                ldsm_x4(addr, b[nf2][0], b[nf2][1], b[nf2][2], b[nf2][3]);
            }
#pragma unroll
            for (int mf = 0; mf < 4; mf++)
#pragma unroll
                for (int nf = 0; nf < 4; nf++) {
                    uint32_t h0 = (nf & 1) ? b[nf >> 1][1] : b[nf >> 1][0];
                    uint32_t h1 = (nf & 1) ? b[nf >> 1][3] : b[nf >> 1][2];
                    mma16816(acc[mf][nf][0], acc[mf][nf][1], acc[mf][nf][2], acc[mf][nf][3],
                             a[mf][0], a[mf][1], a[mf][2], a[mf][3], h0, h1);
                }
        }
    }

    // Epilogue: straight from registers.
#pragma unroll
    for (int mf = 0; mf < 4; mf++) {
        float rs0 = 0.f, rs1 = 0.f;   // mode-3 row-sum partials (rows r0, r0+8)
#pragma unroll
        for (int nf = 0; nf < 4; nf++) {
            const int r0  = m0 + wm * 64 + mf * 16 + (lane >> 2);
            const int col = n0 + wn * 32 + nf * 8 + (lane & 3) * 2;
            float d0 = acc[mf][nf][0], d1 = acc[mf][nf][1];
            float d2 = acc[mf][nf][2], d3 = acc[mf][nf][3];
            if (mode == 2) {
                unsigned short h0 = __half_as_ushort(__float2half_rn(d0));
                unsigned short h1 = __half_as_ushort(__float2half_rn(d1));
                unsigned short h2 = __half_as_ushort(__float2half_rn(d2));
                unsigned short h3 = __half_as_ushort(__float2half_rn(d3));
                *(uint32_t*)(C16 + (size_t)r0 * ldc + col)       = h0 | ((uint32_t)h1 << 16);
                *(uint32_t*)(C16 + (size_t)(r0 + 8) * ldc + col) = h2 | ((uint32_t)h3 << 16);
            } else if (mode == 3) {
                // exp(score) with causal mask (col > row -> 0); accumulate row sums
                float e0 = (col     <= r0    ) ? __expf(d0 * alpha) : 0.f;
                float e1 = (col + 1 <= r0    ) ? __expf(d1 * alpha) : 0.f;
                float e2 = (col     <= r0 + 8) ? __expf(d2 * alpha) : 0.f;
                float e3 = (col + 1 <= r0 + 8) ? __expf(d3 * alpha) : 0.f;
                rs0 += e0 + e1;
                rs1 += e2 + e3;
                unsigned short h0 = __half_as_ushort(__float2half_rn(e0));
                unsigned short h1 = __half_as_ushort(__float2half_rn(e1));
                unsigned short h2 = __half_as_ushort(__float2half_rn(e2));
                unsigned short h3 = __half_as_ushort(__float2half_rn(e3));
                *(uint32_t*)(C16 + (size_t)r0 * ldc + col)       = h0 | ((uint32_t)h1 << 16);
                *(uint32_t*)(C16 + (size_t)(r0 + 8) * ldc + col) = h2 | ((uint32_t)h3 << 16);
            } else {  // mode 4: fp32, row-normalized by aux[row]
                float iv0 = __fdividef(1.f, aux[r0]);
                float iv1 = __fdividef(1.f, aux[r0 + 8]);
                float2 u, v;
                u.x = d0 * iv0; u.y = d1 * iv0;
                v.x = d2 * iv1; v.y = d3 * iv1;
                *(float2*)(C32 + (size_t)r0 * ldc + col)       = u;
                *(float2*)(C32 + (size_t)(r0 + 8) * ldc + col) = v;
            }
        }
        if (mode == 3) {
            // lanes 4k..4k+3 share the same rows; quad-reduce then one atomic
            rs0 += __shfl_xor_sync(0xFFFFFFFF, rs0, 1);
            rs0 += __shfl_xor_sync(0xFFFFFFFF, rs0, 2);
            rs1 += __shfl_xor_sync(0xFFFFFFFF, rs1, 1);
            rs1 += __shfl_xor_sync(0xFFFFFFFF, rs1, 2);
            if ((lane & 3) == 0) {
                const int r0 = m0 + wm * 64 + mf * 16 + (lane >> 2);
                atomicAdd(aux + r0,     rs0);
                atomicAdd(aux + r0 + 8, rs1);
            }
        }
    }
}

// ---------------------------------------------------------------------------
// Merged prep kernel: convert x and W to fp16 + zero g_sum, one launch.
// id < 16384: x blocks; next 3072: W blocks; last 16: zero g_sum.
// ---------------------------------------------------------------------------
__device__ __forceinline__ void hi4_store(float4 v, __half* dh, size_t i) {
    unsigned short h0 = __half_as_ushort(__float2half_rn(v.x));
    unsigned short h1 = __half_as_ushort(__float2half_rn(v.y));
    unsigned short h2 = __half_as_ushort(__float2half_rn(v.z));
    unsigned short h3 = __half_as_ushort(__float2half_rn(v.w));
    *(uint2*)(dh + i) = make_uint2(h0 | ((uint32_t)h1 << 16), h2 | ((uint32_t)h3 << 16));
}

__global__ __launch_bounds__(256) void k_prep(const float* __restrict__ x,
                                              const float* __restrict__ Wq,
                                              const float* __restrict__ Wk,
                                              const float* __restrict__ Wv) {
    const int id = blockIdx.x;
    if (id < 16384) {
        size_t i = ((size_t)id * 256 + threadIdx.x) * 4;
        hi4_store(*(const float4*)(x + i), g_x, i);
    } else if (id < 19456) {
        const int id2 = id - 16384;
        const int z = id2 >> 10;              // 0..2
        const int blk = id2 & 1023;
        const float* src = (z == 0) ? Wq : (z == 1) ? Wk : Wv;
        __half* dst = (z == 0) ? g_wq : (z == 1) ? g_wk : g_wv;
        size_t i = ((size_t)blk * 256 + threadIdx.x) * 4;
        hi4_store(*(const float4*)(src + i), dst, i);
    } else {
        size_t i = (size_t)(id - 19456) * 1024 + threadIdx.x * 4;
        *(float4*)(g_sum + i) = make_float4(0.f, 0.f, 0.f, 0.f);
    }
}

// ---------------------------------------------------------------------------
// Merged projections: 1D grid of 3072 CTAs (256 threads).
//   id in [0,2048): Q/K proj  (z = id>>10, tile = id & 1023 -> 128x8 tiles)
//   id in [2048,3072): Vt proj (per-batch 16x8 tiles)
// ---------------------------------------------------------------------------
__global__ __launch_bounds__(256, 2) void k_proj() {
    const int id = blockIdx.x;
    if (id < 2048) {
        const int z   = id >> 10;
        const int rem = id & 1023;
        const int by  = rem >> 3;       // 0..127 (token tiles)
        const int bx  = rem & 7;        // 0..7   (out-dim tiles)
        gemm128_nt(g_x, z ? g_wk : g_wq, DIMQ, DIMQ, DIMQ / 64,
                   by * 128, bx * 128, DIMQ,
                   nullptr, z ? g_K : g_Q, nullptr, 1.f, 2);
    } else {
        const int id2 = id - 2048;
        const int b   = id2 >> 7;       // 0..7
        const int rem = id2 & 127;
        const int bx  = rem & 15;       // 0..15 (token tiles)
        const int by  = rem >> 4;       // 0..7  (v-dim tiles)
        gemm128_nt(g_wv, g_x + (size_t)b * SEQB * DIMQ, DIMQ, DIMQ, DIMQ / 64,
                   by * 128, bx * 128, SEQB,
                   nullptr, g_Vt + (size_t)b * DIMQ * SEQB, nullptr, 1.f, 2);
    }
}

// Scores: E_b = exp((Q_b @ K_b^T)/32), causal-masked, fp16 out + atomic rowsums.
// Compacted grid: blockIdx.x = triangular tile index t in [0,136), batch = y.
__global__ __launch_bounds__(256, 2) void k_scores() {
    const int t = blockIdx.x, b = blockIdx.y;
    int bm = (int)((sqrtf(8.f * (float)t + 1.f) - 1.f) * 0.5f);
    if ((bm + 1) * (bm + 2) / 2 <= t) bm++;
    else if (bm * (bm + 1) / 2 > t) bm--;
    const int bn = t - bm * (bm + 1) / 2;
    gemm128_nt(g_Q + (size_t)b * SEQB * DIMQ, g_K + (size_t)b * SEQB * DIMQ,
               DIMQ, DIMQ, DIMQ / 64, bm * 128, bn * 128, SEQB,
               nullptr, g_E + (size_t)b * SEQB * SEQB,
               g_sum + (size_t)b * SEQB, 0.03125f, 3);
}

// Out: O_b = (E_b @ Vt_b^T) / sum[row], K truncated at (bm+1)*128.
// bm reversed so the longest-K CTAs launch first (better wave packing).
__global__ __launch_bounds__(256, 2) void k_out(float* __restrict__ out) {
    const int bn = blockIdx.x, bm = 15 - blockIdx.y, b = blockIdx.z;
    gemm128_nt(g_E + (size_t)b * SEQB * SEQB, g_Vt + (size_t)b * DIMQ * SEQB,
               SEQB, SEQB, (bm + 1) * 2, bm * 128, bn * 128, DIMQ,
               out + (size_t)b * SEQB * DIMQ, nullptr,
               g_sum + (size_t)b * SEQB, 1.f, 4);
}

// ---------------------------------------------------------------------------
extern "C" void kernel_launch(void* const* d_in, const int* in_sizes, int n_in,
                              void* d_out, int out_size)
{
    const float* x  = (const float*)d_in[0];
    const float* Wq = (const float*)d_in[1];
    const float* Wk = (const float*)d_in[2];
    const float* Wv = (const float*)d_in[3];
    float* out = (float*)d_out;

    cudaFuncSetAttribute(k_proj,   cudaFuncAttributeMaxDynamicSharedMemorySize, SMEM_SZ);
    cudaFuncSetAttribute(k_scores, cudaFuncAttributeMaxDynamicSharedMemorySize, SMEM_SZ);
    cudaFuncSetAttribute(k_out,    cudaFuncAttributeMaxDynamicSharedMemorySize, SMEM_SZ);

    k_prep  <<<19472, 256>>>(x, Wq, Wk, Wv);                             // conv x/W + zero sums
    k_proj  <<<3072, 256, SMEM_SZ>>>();                                  // merged QK + Vt
    k_scores<<<dim3(136, NB), 256, SMEM_SZ>>>();                         // 136 tri tiles x 8
    k_out   <<<dim3(DIMQ / 128, SEQB / 128, NB), 256, SMEM_SZ>>>(out);   // (8,16,8)
}